// round 1
// baseline (speedup 1.0000x reference)
#include <cuda_runtime.h>
#include <cuda_bf16.h>
#include <cstdint>

#define B_ROWS 2048
#define L_SEQ 50
#define EMBED 128
#define OUT_LD 50000
#define CUT0 12500
#define CUT1 25000
#define HEAD_N 12502
#define H0_DIM 64
#define H1_DIM 32
#define N_T1 25000
#define MAX_TILES 256
#define TS 136   /* smem tile row stride in bf16 elems (128 + 8 pad) */

#define NEG_INF (__int_as_float(0xff800000))

// ---------------- scratch (static device memory; no allocations) ----------------
__device__ __align__(16) __nv_bfloat16 g_pooled[B_ROWS * EMBED];
__device__ __align__(16) __nv_bfloat16 g_headw[HEAD_N * EMBED];
__device__ __align__(16) __nv_bfloat16 g_t0p[H0_DIM * EMBED];
__device__ __align__(16) __nv_bfloat16 g_t1p[H1_DIM * EMBED];
__device__ __align__(16) __nv_bfloat16 g_t0o[CUT0 * H0_DIM];
__device__ __align__(16) __nv_bfloat16 g_t1o[N_T1 * H1_DIM];
__device__ __align__(16) __nv_bfloat16 g_h0[B_ROWS * H0_DIM];
__device__ __align__(16) __nv_bfloat16 g_h1[B_ROWS * H1_DIM];
__device__ float g_stats_m[3 * B_ROWS * MAX_TILES];
__device__ float g_stats_s[3 * B_ROWS * MAX_TILES];
__device__ float g_extra[B_ROWS * 2];
__device__ float g_adds[B_ROWS * 3];

// ---------------- fp32 -> bf16 convert ----------------
__global__ void cvt_kernel(const float* __restrict__ src, __nv_bfloat16* __restrict__ dst, int n) {
    for (int i = blockIdx.x * blockDim.x + threadIdx.x; i < n; i += gridDim.x * blockDim.x)
        dst[i] = __float2bfloat16(src[i]);
}

// ---------------- embedding-bag pooling ----------------
__global__ void pool_kernel(const int* __restrict__ x, const float* __restrict__ emb,
                            __nv_bfloat16* __restrict__ pooled) {
    int b = blockIdx.x;
    int tid = threadIdx.x;  // 128 threads = one embed dim each
    __shared__ int xs[L_SEQ];
    if (tid < L_SEQ) xs[tid] = x[b * L_SEQ + tid];
    __syncthreads();
    float acc = 0.f;
    int cnt = 0;
    #pragma unroll
    for (int l = 0; l < L_SEQ; l++) {
        int idx = xs[l];
        if (idx != 0) {
            cnt++;
            acc += emb[(size_t)idx * EMBED + tid];
        }
    }
    float c = (float)(cnt < 1 ? 1 : cnt);
    pooled[b * EMBED + tid] = __float2bfloat16(acc / c);
}

// ---------------- bf16 mma GEMM: C[b][n] = sum_k A[b][k] * W[n][k] ----------------
// mode 0: write bf16 to outBf (ld = ldOutBf), no stats.
// mode 1: write fp32 logits to out (col offset colOff; isHead routes cols >= CUT0
//         to g_extra) and per-(row,tile) max/sumexp stats to g_stats_*.
__global__ void __launch_bounds__(256, 2)
gemm_kernel(const __nv_bfloat16* __restrict__ A, const __nv_bfloat16* __restrict__ W,
            int N, int K,
            float* __restrict__ out, int colOff, int group, int isHead,
            __nv_bfloat16* __restrict__ outBf, int ldOutBf, int mode) {
    extern __shared__ __nv_bfloat16 smem[];
    __nv_bfloat16* As = smem;               // [128][TS]
    __nv_bfloat16* Ws = smem + 128 * TS;    // [128][TS]
    __shared__ float red_m[128][4];
    __shared__ float red_s[128][4];

    int tid = threadIdx.x;
    int m0 = blockIdx.y * 128;
    int n0 = blockIdx.x * 128;
    int kVec = K >> 3;              // uint4 chunks per row
    int totA = 128 * kVec;

    for (int i = tid; i < totA; i += 256) {
        int r = i / kVec, c = i - r * kVec;
        uint4 v = *reinterpret_cast<const uint4*>(A + (size_t)(m0 + r) * K + c * 8);
        *reinterpret_cast<uint4*>(As + r * TS + c * 8) = v;
    }
    for (int i = tid; i < totA; i += 256) {
        int r = i / kVec, c = i - r * kVec;
        int wr = n0 + r;
        uint4 v = make_uint4(0u, 0u, 0u, 0u);
        if (wr < N) v = *reinterpret_cast<const uint4*>(W + (size_t)wr * K + c * 8);
        *reinterpret_cast<uint4*>(Ws + r * TS + c * 8) = v;
    }
    __syncthreads();

    int warp = tid >> 5, lane = tid & 31;
    int g = lane >> 2, t4 = lane & 3;
    int wm = (warp >> 2) * 64;   // 2 warps in M
    int wn = (warp & 3) * 32;    // 4 warps in N

    float acc[4][4][4];
    #pragma unroll
    for (int mt = 0; mt < 4; mt++)
        #pragma unroll
        for (int nt = 0; nt < 4; nt++)
            #pragma unroll
            for (int i = 0; i < 4; i++) acc[mt][nt][i] = 0.f;

    for (int k0 = 0; k0 < K; k0 += 16) {
        uint32_t a[4][4], b[4][2];
        #pragma unroll
        for (int mt = 0; mt < 4; mt++) {
            const __nv_bfloat16* p = As + (wm + mt * 16 + g) * TS + k0 + t4 * 2;
            a[mt][0] = *reinterpret_cast<const uint32_t*>(p);
            a[mt][2] = *reinterpret_cast<const uint32_t*>(p + 8);
            const __nv_bfloat16* p2 = p + 8 * TS;
            a[mt][1] = *reinterpret_cast<const uint32_t*>(p2);
            a[mt][3] = *reinterpret_cast<const uint32_t*>(p2 + 8);
        }
        #pragma unroll
        for (int nt = 0; nt < 4; nt++) {
            const __nv_bfloat16* p = Ws + (wn + nt * 8 + g) * TS + k0 + t4 * 2;
            b[nt][0] = *reinterpret_cast<const uint32_t*>(p);
            b[nt][1] = *reinterpret_cast<const uint32_t*>(p + 8);
        }
        #pragma unroll
        for (int mt = 0; mt < 4; mt++)
            #pragma unroll
            for (int nt = 0; nt < 4; nt++)
                asm volatile(
                    "mma.sync.aligned.m16n8k16.row.col.f32.bf16.bf16.f32 "
                    "{%0,%1,%2,%3}, {%4,%5,%6,%7}, {%8,%9}, {%0,%1,%2,%3};"
                    : "+f"(acc[mt][nt][0]), "+f"(acc[mt][nt][1]),
                      "+f"(acc[mt][nt][2]), "+f"(acc[mt][nt][3])
                    : "r"(a[mt][0]), "r"(a[mt][1]), "r"(a[mt][2]), "r"(a[mt][3]),
                      "r"(b[nt][0]), "r"(b[nt][1]));
    }

    if (mode == 0) {
        // plain bf16 output (small projection GEMMs)
        #pragma unroll
        for (int mt = 0; mt < 4; mt++)
            #pragma unroll
            for (int half = 0; half < 2; half++) {
                int gr = m0 + wm + mt * 16 + g + half * 8;
                #pragma unroll
                for (int nt = 0; nt < 4; nt++)
                    #pragma unroll
                    for (int h = 0; h < 2; h++) {
                        int gc = n0 + wn + nt * 8 + t4 * 2 + h;
                        if (gc < N)
                            outBf[(size_t)gr * ldOutBf + gc] =
                                __float2bfloat16(acc[mt][nt][half * 2 + h]);
                    }
            }
        return;
    }

    // mode 1: store logits + per-(row, tile) stats
    int wnId = warp & 3;
    #pragma unroll
    for (int mt = 0; mt < 4; mt++) {
        #pragma unroll
        for (int half = 0; half < 2; half++) {
            int rowRel = wm + mt * 16 + g + half * 8;
            size_t gr = (size_t)(m0 + rowRel);
            float m = NEG_INF;
            float vv[8];
            bool ok[8];
            #pragma unroll
            for (int nt = 0; nt < 4; nt++)
                #pragma unroll
                for (int h = 0; h < 2; h++) {
                    float v = acc[mt][nt][half * 2 + h];
                    int gc = n0 + wn + nt * 8 + t4 * 2 + h;
                    int ix = nt * 2 + h;
                    vv[ix] = v;
                    ok[ix] = (gc < N);
                    if (ok[ix]) {
                        m = fmaxf(m, v);
                        if (isHead) {
                            if (gc < CUT0) out[gr * OUT_LD + gc] = v;
                            else g_extra[gr * 2 + (gc - CUT0)] = v;
                        } else {
                            out[gr * OUT_LD + colOff + gc] = v;
                        }
                    }
                }
            m = fmaxf(m, __shfl_xor_sync(0xffffffffu, m, 1));
            m = fmaxf(m, __shfl_xor_sync(0xffffffffu, m, 2));
            float s = 0.f;
            #pragma unroll
            for (int ix = 0; ix < 8; ix++)
                if (ok[ix]) s += __expf(vv[ix] - m);
            s += __shfl_xor_sync(0xffffffffu, s, 1);
            s += __shfl_xor_sync(0xffffffffu, s, 2);
            if (t4 == 0) {
                red_m[rowRel][wnId] = m;
                red_s[rowRel][wnId] = s;
            }
        }
    }
    __syncthreads();
    if (tid < 128) {
        int r = tid;
        float M = red_m[r][0];
        #pragma unroll
        for (int i = 1; i < 4; i++) M = fmaxf(M, red_m[r][i]);
        float S = 0.f;
        #pragma unroll
        for (int i = 0; i < 4; i++) {
            float si = red_s[r][i];
            if (si > 0.f) S += si * __expf(red_m[r][i] - M);
        }
        int grow = m0 + r;
        size_t sidx = ((size_t)group * B_ROWS + grow) * MAX_TILES + blockIdx.x;
        g_stats_m[sidx] = M;
        g_stats_s[sidx] = S;
    }
}

// ---------------- combine per-tile stats -> per-row additive constants ----------------
__global__ void combine_kernel() {
    int r = blockIdx.x;
    int tid = threadIdx.x;
    __shared__ float red[256];
    __shared__ float lse[3];
    const int nTiles0 = (HEAD_N + 127) / 128;   // 98
    const int nTiles1 = (CUT0 + 127) / 128;     // 98
    const int nTiles2 = (N_T1 + 127) / 128;     // 196
    #pragma unroll
    for (int grp = 0; grp < 3; grp++) {
        int nT = (grp == 0) ? nTiles0 : (grp == 1 ? nTiles1 : nTiles2);
        const float* pm = g_stats_m + ((size_t)grp * B_ROWS + r) * MAX_TILES;
        const float* ps = g_stats_s + ((size_t)grp * B_ROWS + r) * MAX_TILES;
        float m = NEG_INF;
        for (int t = tid; t < nT; t += 256) m = fmaxf(m, pm[t]);
        red[tid] = m;
        __syncthreads();
        for (int off = 128; off > 0; off >>= 1) {
            if (tid < off) red[tid] = fmaxf(red[tid], red[tid + off]);
            __syncthreads();
        }
        float M = red[0];
        __syncthreads();
        float s = 0.f;
        for (int t = tid; t < nT; t += 256) {
            float si = ps[t];
            if (si > 0.f) s += si * __expf(pm[t] - M);
        }
        red[tid] = s;
        __syncthreads();
        for (int off = 128; off > 0; off >>= 1) {
            if (tid < off) red[tid] += red[tid + off];
            __syncthreads();
        }
        if (tid == 0) lse[grp] = M + logf(red[0]);
        __syncthreads();
    }
    if (tid == 0) {
        float lh = lse[0];
        g_adds[r * 3 + 0] = -lh;
        g_adds[r * 3 + 1] = g_extra[r * 2 + 0] - lh - lse[1];
        g_adds[r * 3 + 2] = g_extra[r * 2 + 1] - lh - lse[2];
    }
}

// ---------------- finalize: out += per-(row, group) constant ----------------
__global__ void finalize_kernel(float* __restrict__ out) {
    const int perRow = OUT_LD / 4;   // 12500 float4 per row
    const int total = B_ROWS * perRow;
    for (int i = blockIdx.x * blockDim.x + threadIdx.x; i < total;
         i += gridDim.x * blockDim.x) {
        int r = i / perRow;
        int c4 = i - r * perRow;
        int grp = (c4 < CUT0 / 4) ? 0 : (c4 < CUT1 / 4 ? 1 : 2);
        float add = g_adds[r * 3 + grp];
        float4 v = reinterpret_cast<float4*>(out)[i];
        v.x += add; v.y += add; v.z += add; v.w += add;
        reinterpret_cast<float4*>(out)[i] = v;
    }
}

// ---------------- launch ----------------
extern "C" void kernel_launch(void* const* d_in, const int* in_sizes, int n_in,
                              void* d_out, int out_size) {
    const int*   x        = (const int*)d_in[0];
    const float* emb      = (const float*)d_in[1];
    const float* head_w_f = (const float*)d_in[2];
    const float* t0p_f    = (const float*)d_in[3];
    const float* t0o_f    = (const float*)d_in[4];
    const float* t1p_f    = (const float*)d_in[5];
    const float* t1o_f    = (const float*)d_in[6];
    float* out = (float*)d_out;

    __nv_bfloat16 *p_pooled, *p_headw, *p_t0p, *p_t1p, *p_t0o, *p_t1o, *p_h0, *p_h1;
    cudaGetSymbolAddress((void**)&p_pooled, g_pooled);
    cudaGetSymbolAddress((void**)&p_headw, g_headw);
    cudaGetSymbolAddress((void**)&p_t0p, g_t0p);
    cudaGetSymbolAddress((void**)&p_t1p, g_t1p);
    cudaGetSymbolAddress((void**)&p_t0o, g_t0o);
    cudaGetSymbolAddress((void**)&p_t1o, g_t1o);
    cudaGetSymbolAddress((void**)&p_h0, g_h0);
    cudaGetSymbolAddress((void**)&p_h1, g_h1);

    const int SMEM_BYTES = 2 * 128 * TS * (int)sizeof(__nv_bfloat16);  // 69632
    cudaFuncSetAttribute(gemm_kernel, cudaFuncAttributeMaxDynamicSharedMemorySize, SMEM_BYTES);

    // weight converts (bf16)
    cvt_kernel<<<512, 256>>>(head_w_f, p_headw, HEAD_N * EMBED);
    cvt_kernel<<<8,   256>>>(t0p_f, p_t0p, H0_DIM * EMBED);
    cvt_kernel<<<4,   256>>>(t1p_f, p_t1p, H1_DIM * EMBED);
    cvt_kernel<<<256, 256>>>(t0o_f, p_t0o, CUT0 * H0_DIM);
    cvt_kernel<<<256, 256>>>(t1o_f, p_t1o, N_T1 * H1_DIM);

    // pooling
    pool_kernel<<<B_ROWS, 128>>>(x, emb, p_pooled);

    dim3 blk(256);
    // projections: h0 = pooled @ t0_proj^T, h1 = pooled @ t1_proj^T
    gemm_kernel<<<dim3(1, 16), blk, SMEM_BYTES>>>(p_pooled, p_t0p, H0_DIM, EMBED,
                                                  nullptr, 0, 0, 0, p_h0, H0_DIM, 0);
    gemm_kernel<<<dim3(1, 16), blk, SMEM_BYTES>>>(p_pooled, p_t1p, H1_DIM, EMBED,
                                                  nullptr, 0, 0, 0, p_h1, H1_DIM, 0);
    // big logit GEMMs with stats
    gemm_kernel<<<dim3(98, 16), blk, SMEM_BYTES>>>(p_pooled, p_headw, HEAD_N, EMBED,
                                                   out, 0, 0, 1, nullptr, 0, 1);
    gemm_kernel<<<dim3(98, 16), blk, SMEM_BYTES>>>(p_h0, p_t0o, CUT0, H0_DIM,
                                                   out, CUT0, 1, 0, nullptr, 0, 1);
    gemm_kernel<<<dim3(196, 16), blk, SMEM_BYTES>>>(p_h1, p_t1o, N_T1, H1_DIM,
                                                    out, CUT1, 2, 0, nullptr, 0, 1);
    // softmax stat combine + finalize
    combine_kernel<<<B_ROWS, 256>>>();
    finalize_kernel<<<4096, 256>>>(out);
}

// round 2
// speedup vs baseline: 1.4041x; 1.4041x over previous
#include <cuda_runtime.h>
#include <cuda_bf16.h>
#include <cstdint>

#define B_ROWS 2048
#define L_SEQ 50
#define EMBED 128
#define OUT_LD 50000
#define CUT0 12500
#define CUT1 25000
#define HEAD_N 12502
#define H0_DIM 64
#define H1_DIM 32
#define N_T1 25000
#define MAX_TILES 256

// ---------------- scratch (static device memory; no allocations) ----------------
__device__ __align__(16) __nv_bfloat16 g_pooled[B_ROWS * EMBED];
__device__ __align__(16) __nv_bfloat16 g_h0[B_ROWS * H0_DIM];
__device__ __align__(16) __nv_bfloat16 g_h1[B_ROWS * H1_DIM];
__device__ float g_stats_s[3 * B_ROWS * MAX_TILES];
__device__ float g_extra[B_ROWS * 2];
__device__ float g_adds[B_ROWS * 3];

__device__ __forceinline__ uint32_t smem_u32(const void* p) {
    return (uint32_t)__cvta_generic_to_shared(p);
}

// ---------------- embedding-bag pooling ----------------
__global__ void pool_kernel(const int* __restrict__ x, const float* __restrict__ emb,
                            __nv_bfloat16* __restrict__ pooled) {
    int b = blockIdx.x;
    int tid = threadIdx.x;  // 128 threads = one embed dim each
    __shared__ int xs[L_SEQ];
    if (tid < L_SEQ) xs[tid] = x[b * L_SEQ + tid];
    __syncthreads();
    float acc = 0.f;
    int cnt = 0;
    #pragma unroll
    for (int l = 0; l < L_SEQ; l++) {
        int idx = xs[l];
        if (idx != 0) {
            cnt++;
            acc += emb[(size_t)idx * EMBED + tid];
        }
    }
    float c = (float)(cnt < 1 ? 1 : cnt);
    pooled[b * EMBED + tid] = __float2bfloat16(acc / c);
}

// ---------------- bf16 mma GEMM (W loaded as fp32, converted in smem fill) ----------------
// C[b][n] = sum_k A[b][k] * W[n][k]
// MODE 0: write bf16 to outBf (projection GEMMs), bound NW.
// MODE 1: stats only: per-(row,tile) sum(exp(logit)) over cols < NW -> g_stats_s;
//         if isHead, capture logits at cols CUT0/CUT0+1 into g_extra.
// MODE 2: out[row][colOff+col] = logit + g_adds[row*3+group] for cols < NS.
template <int K, int MODE>
__global__ void __launch_bounds__(256, 2)
gemm_t(const __nv_bfloat16* __restrict__ A, const float* __restrict__ Wf,
       int NW, int NS,
       float* __restrict__ out, int colOff, int group, int isHead,
       __nv_bfloat16* __restrict__ outBf, int ldOutBf) {
    constexpr int TS = K + 8;     // smem row stride (bf16 elems)
    extern __shared__ __nv_bfloat16 smem[];
    __nv_bfloat16* As = smem;             // [128][TS]
    __nv_bfloat16* Ws = smem + 128 * TS;  // [128][TS]
    __shared__ float red_s[128][4];
    __shared__ float adds_s[128];

    int tid = threadIdx.x;
    int m0 = blockIdx.y * 128;
    int n0 = blockIdx.x * 128;

    if (MODE == 2) {
        if (tid < 128) adds_s[tid] = g_adds[(m0 + tid) * 3 + group];
    }

    // A tile: bf16, uint4 (8 elems) per chunk
    {
        constexpr int kVec = K >> 3;
        constexpr int totA = 128 * kVec;
        #pragma unroll
        for (int i = tid; i < totA; i += 256) {
            int r = i / kVec, c = i - r * kVec;
            uint4 v = *reinterpret_cast<const uint4*>(A + (size_t)(m0 + r) * K + c * 8);
            *reinterpret_cast<uint4*>(As + r * TS + c * 8) = v;
        }
    }
    // W tile: fp32 -> bf16 convert, float4 (4 elems) per chunk
    {
        constexpr int kVecW = K >> 2;
        constexpr int totW = 128 * kVecW;
        #pragma unroll
        for (int i = tid; i < totW; i += 256) {
            int r = i / kVecW, c = i - r * kVecW;
            int wr = n0 + r;
            uint2 pk = make_uint2(0u, 0u);
            if (wr < NW) {
                float4 v = *reinterpret_cast<const float4*>(Wf + (size_t)wr * K + c * 4);
                __nv_bfloat162 lo = __float22bfloat162_rn(make_float2(v.x, v.y));
                __nv_bfloat162 hi = __float22bfloat162_rn(make_float2(v.z, v.w));
                pk.x = *reinterpret_cast<uint32_t*>(&lo);
                pk.y = *reinterpret_cast<uint32_t*>(&hi);
            }
            *reinterpret_cast<uint2*>(Ws + r * TS + c * 4) = pk;
        }
    }
    __syncthreads();

    int warp = tid >> 5, lane = tid & 31;
    int g = lane >> 2, t4 = lane & 3;
    int wm = (warp >> 2) * 64;   // 2 warps in M
    int wn = (warp & 3) * 32;    // 4 warps in N

    // ldmatrix base addresses
    uint32_t aBase[4], bBase[2];
    {
        int arow = (lane & 7) + ((lane & 8) ? 8 : 0);   // (q&1)*8 + lane&7 == lane&15
        int akoff = (lane >> 4) * 8;
        #pragma unroll
        for (int mt = 0; mt < 4; mt++)
            aBase[mt] = smem_u32(As + (wm + mt * 16 + (lane & 15)) * TS + akoff);
        (void)arow;
        int q = lane >> 3;
        int brow_off = (q >> 1) * 8 + (lane & 7);
        int bkoff = (q & 1) * 8;
        #pragma unroll
        for (int p = 0; p < 2; p++)
            bBase[p] = smem_u32(Ws + (wn + p * 16 + brow_off) * TS + bkoff);
    }

    float acc[4][4][4];
    #pragma unroll
    for (int mt = 0; mt < 4; mt++)
        #pragma unroll
        for (int nt = 0; nt < 4; nt++)
            #pragma unroll
            for (int i = 0; i < 4; i++) acc[mt][nt][i] = 0.f;

    #pragma unroll
    for (int k0 = 0; k0 < K; k0 += 16) {
        uint32_t a[4][4], b[2][4];
        #pragma unroll
        for (int mt = 0; mt < 4; mt++)
            asm volatile("ldmatrix.sync.aligned.m8n8.x4.shared.b16 {%0,%1,%2,%3}, [%4];"
                         : "=r"(a[mt][0]), "=r"(a[mt][1]), "=r"(a[mt][2]), "=r"(a[mt][3])
                         : "r"(aBase[mt] + k0 * 2));
        #pragma unroll
        for (int p = 0; p < 2; p++)
            asm volatile("ldmatrix.sync.aligned.m8n8.x4.shared.b16 {%0,%1,%2,%3}, [%4];"
                         : "=r"(b[p][0]), "=r"(b[p][1]), "=r"(b[p][2]), "=r"(b[p][3])
                         : "r"(bBase[p] + k0 * 2));
        #pragma unroll
        for (int mt = 0; mt < 4; mt++)
            #pragma unroll
            for (int nt = 0; nt < 4; nt++) {
                const uint32_t* bb = &b[nt >> 1][(nt & 1) * 2];
                asm volatile(
                    "mma.sync.aligned.m16n8k16.row.col.f32.bf16.bf16.f32 "
                    "{%0,%1,%2,%3}, {%4,%5,%6,%7}, {%8,%9}, {%0,%1,%2,%3};"
                    : "+f"(acc[mt][nt][0]), "+f"(acc[mt][nt][1]),
                      "+f"(acc[mt][nt][2]), "+f"(acc[mt][nt][3])
                    : "r"(a[mt][0]), "r"(a[mt][1]), "r"(a[mt][2]), "r"(a[mt][3]),
                      "r"(bb[0]), "r"(bb[1]));
            }
    }

    if (MODE == 0) {
        #pragma unroll
        for (int mt = 0; mt < 4; mt++)
            #pragma unroll
            for (int half = 0; half < 2; half++) {
                int gr = m0 + wm + mt * 16 + g + half * 8;
                #pragma unroll
                for (int nt = 0; nt < 4; nt++)
                    #pragma unroll
                    for (int h = 0; h < 2; h++) {
                        int gc = n0 + wn + nt * 8 + t4 * 2 + h;
                        if (gc < NW)
                            outBf[(size_t)gr * ldOutBf + gc] =
                                __float2bfloat16(acc[mt][nt][half * 2 + h]);
                    }
            }
        return;
    }

    if (MODE == 1) {
        int wnId = warp & 3;
        #pragma unroll
        for (int mt = 0; mt < 4; mt++) {
            #pragma unroll
            for (int half = 0; half < 2; half++) {
                int rowRel = wm + mt * 16 + g + half * 8;
                size_t gr = (size_t)(m0 + rowRel);
                float s = 0.f;
                #pragma unroll
                for (int nt = 0; nt < 4; nt++)
                    #pragma unroll
                    for (int h = 0; h < 2; h++) {
                        int gc = n0 + wn + nt * 8 + t4 * 2 + h;
                        float v = acc[mt][nt][half * 2 + h];
                        if (gc < NW) {
                            s += __expf(v);
                            if (isHead && gc >= CUT0)
                                g_extra[gr * 2 + (gc - CUT0)] = v;
                        }
                    }
                s += __shfl_xor_sync(0xffffffffu, s, 1);
                s += __shfl_xor_sync(0xffffffffu, s, 2);
                if (t4 == 0) red_s[rowRel][wnId] = s;
            }
        }
        __syncthreads();
        if (tid < 128) {
            float S = red_s[tid][0] + red_s[tid][1] + red_s[tid][2] + red_s[tid][3];
            g_stats_s[((size_t)group * B_ROWS + m0 + tid) * MAX_TILES + blockIdx.x] = S;
        }
        return;
    }

    // MODE 2: fused add + fp32 store (float2, cols are even-aligned pairs)
    #pragma unroll
    for (int mt = 0; mt < 4; mt++)
        #pragma unroll
        for (int half = 0; half < 2; half++) {
            int rowRel = wm + mt * 16 + g + half * 8;
            size_t gr = (size_t)(m0 + rowRel);
            float add = adds_s[rowRel];
            #pragma unroll
            for (int nt = 0; nt < 4; nt++) {
                int gc = n0 + wn + nt * 8 + t4 * 2;
                if (gc < NS) {
                    float2 w = make_float2(acc[mt][nt][half * 2 + 0] + add,
                                           acc[mt][nt][half * 2 + 1] + add);
                    *reinterpret_cast<float2*>(out + gr * OUT_LD + colOff + gc) = w;
                }
            }
        }
}

// ---------------- combine per-tile sumexp -> per-row additive constants ----------------
__global__ void combine_kernel() {
    int r = blockIdx.x * 8 + (threadIdx.x >> 5);
    int lane = threadIdx.x & 31;
    const int nT[3] = { (HEAD_N + 127) / 128, (CUT0 + 127) / 128, (N_T1 + 127) / 128 };
    float lse[3];
    #pragma unroll
    for (int grp = 0; grp < 3; grp++) {
        const float* ps = g_stats_s + ((size_t)grp * B_ROWS + r) * MAX_TILES;
        float s = 0.f;
        for (int t = lane; t < nT[grp]; t += 32) s += ps[t];
        #pragma unroll
        for (int off = 16; off > 0; off >>= 1)
            s += __shfl_xor_sync(0xffffffffu, s, off);
        lse[grp] = logf(s);
    }
    if (lane == 0) {
        float lh = lse[0];
        g_adds[r * 3 + 0] = -lh;
        g_adds[r * 3 + 1] = g_extra[r * 2 + 0] - lh - lse[1];
        g_adds[r * 3 + 2] = g_extra[r * 2 + 1] - lh - lse[2];
    }
}

// ---------------- launch ----------------
extern "C" void kernel_launch(void* const* d_in, const int* in_sizes, int n_in,
                              void* d_out, int out_size) {
    const int*   x        = (const int*)d_in[0];
    const float* emb      = (const float*)d_in[1];
    const float* head_w_f = (const float*)d_in[2];
    const float* t0p_f    = (const float*)d_in[3];
    const float* t0o_f    = (const float*)d_in[4];
    const float* t1p_f    = (const float*)d_in[5];
    const float* t1o_f    = (const float*)d_in[6];
    float* out = (float*)d_out;

    __nv_bfloat16 *p_pooled, *p_h0, *p_h1;
    cudaGetSymbolAddress((void**)&p_pooled, g_pooled);
    cudaGetSymbolAddress((void**)&p_h0, g_h0);
    cudaGetSymbolAddress((void**)&p_h1, g_h1);

    const int SM128 = 2 * 128 * (128 + 8) * (int)sizeof(__nv_bfloat16);  // 69632
    const int SM64  = 2 * 128 * (64 + 8) * (int)sizeof(__nv_bfloat16);   // 36864
    const int SM32  = 2 * 128 * (32 + 8) * (int)sizeof(__nv_bfloat16);   // 20480
    static bool attrDone = false;
    if (!attrDone) {
        cudaFuncSetAttribute(gemm_t<128, 0>, cudaFuncAttributeMaxDynamicSharedMemorySize, SM128);
        cudaFuncSetAttribute(gemm_t<128, 1>, cudaFuncAttributeMaxDynamicSharedMemorySize, SM128);
        cudaFuncSetAttribute(gemm_t<128, 2>, cudaFuncAttributeMaxDynamicSharedMemorySize, SM128);
        attrDone = true;
    }

    // pooling (bf16 pooled vector)
    pool_kernel<<<B_ROWS, 128>>>(x, emb, p_pooled);

    dim3 blk(256);
    // projections: h0 = pooled @ t0_proj^T (bf16), h1 = pooled @ t1_proj^T
    gemm_t<128, 0><<<dim3(1, 16), blk, SM128>>>(p_pooled, t0p_f, H0_DIM, H0_DIM,
                                                nullptr, 0, 0, 0, p_h0, H0_DIM);
    gemm_t<128, 0><<<dim3(1, 16), blk, SM128>>>(p_pooled, t1p_f, H1_DIM, H1_DIM,
                                                nullptr, 0, 0, 0, p_h1, H1_DIM);
    // pass A: stats only
    gemm_t<128, 1><<<dim3(98, 16), blk, SM128>>>(p_pooled, head_w_f, HEAD_N, HEAD_N,
                                                 nullptr, 0, 0, 1, nullptr, 0);
    gemm_t<64, 1><<<dim3(98, 16), blk, SM64>>>(p_h0, t0o_f, CUT0, CUT0,
                                               nullptr, 0, 1, 0, nullptr, 0);
    gemm_t<32, 1><<<dim3(196, 16), blk, SM32>>>(p_h1, t1o_f, N_T1, N_T1,
                                                nullptr, 0, 2, 0, nullptr, 0);
    // combine sumexp -> per-row adds
    combine_kernel<<<B_ROWS / 8, 256>>>();
    // pass B: recompute + fused add + single store of the 410MB output
    gemm_t<128, 2><<<dim3(98, 16), blk, SM128>>>(p_pooled, head_w_f, HEAD_N, CUT0,
                                                 out, 0, 0, 1, nullptr, 0);
    gemm_t<64, 2><<<dim3(98, 16), blk, SM64>>>(p_h0, t0o_f, CUT0, CUT0,
                                               out, CUT0, 1, 0, nullptr, 0);
    gemm_t<32, 2><<<dim3(196, 16), blk, SM32>>>(p_h1, t1o_f, N_T1, N_T1,
                                                out, CUT1, 2, 0, nullptr, 0);
}

// round 3
// speedup vs baseline: 1.7234x; 1.2274x over previous
#include <cuda_runtime.h>
#include <cuda_bf16.h>
#include <cstdint>

#define B_ROWS 2048
#define L_SEQ 50
#define EMBED 128
#define OUT_LD 50000
#define CUT0 12500
#define CUT1 25000
#define HEAD_N 12502
#define H0_DIM 64
#define H1_DIM 32
#define N_T1 25000
#define TILE_STRIDE 400   /* stats stride per row (max 391 tiles) */

// tiles per group with N-tile = 64
#define NT_HEAD 196   /* ceil(12502/64) */
#define NT_T0   196
#define NT_T1   391

// ---------------- scratch (static device memory; no allocations) ----------------
__device__ __align__(16) __nv_bfloat16 g_pooled[B_ROWS * EMBED];
__device__ __align__(16) __nv_bfloat16 g_headw[HEAD_N * EMBED];
__device__ __align__(16) __nv_bfloat16 g_t0o[CUT0 * H0_DIM];
__device__ __align__(16) __nv_bfloat16 g_t1o[N_T1 * H1_DIM];
__device__ __align__(16) __nv_bfloat16 g_t0p[H0_DIM * EMBED];
__device__ __align__(16) __nv_bfloat16 g_t1p[H1_DIM * EMBED];
__device__ __align__(16) __nv_bfloat16 g_h0[B_ROWS * H0_DIM];
__device__ __align__(16) __nv_bfloat16 g_h1[B_ROWS * H1_DIM];
__device__ float g_stats_s[3 * B_ROWS * TILE_STRIDE];
__device__ float g_extra[B_ROWS * 2];
__device__ float g_adds[B_ROWS * 3];

__device__ __forceinline__ uint32_t smem_u32(const void* p) {
    return (uint32_t)__cvta_generic_to_shared(p);
}

// ---------------- segmented fp32 -> bf16 convert of all weights ----------------
#define NV_H  400064u   /* 12502*128/4 */
#define NV_0  200000u   /* 12500*64/4 */
#define NV_1  200000u   /* 25000*32/4 */
#define NV_P0 2048u
#define NV_P1 1024u
__global__ void cvt_all(const float* __restrict__ wh, const float* __restrict__ w0,
                        const float* __restrict__ w1, const float* __restrict__ p0,
                        const float* __restrict__ p1) {
    const unsigned total = NV_H + NV_0 + NV_1 + NV_P0 + NV_P1;
    for (unsigned i = blockIdx.x * blockDim.x + threadIdx.x; i < total;
         i += gridDim.x * blockDim.x) {
        const float* src; __nv_bfloat16* dst; unsigned j = i;
        if (j < NV_H) { src = wh; dst = g_headw; }
        else if ((j -= NV_H) < NV_0) { src = w0; dst = g_t0o; }
        else if ((j -= NV_0) < NV_1) { src = w1; dst = g_t1o; }
        else if ((j -= NV_1) < NV_P0) { src = p0; dst = g_t0p; }
        else { j -= NV_P0; src = p1; dst = g_t1p; }
        float4 v = reinterpret_cast<const float4*>(src)[j];
        __nv_bfloat162 lo = __float22bfloat162_rn(make_float2(v.x, v.y));
        __nv_bfloat162 hi = __float22bfloat162_rn(make_float2(v.z, v.w));
        uint2 pk;
        pk.x = *reinterpret_cast<uint32_t*>(&lo);
        pk.y = *reinterpret_cast<uint32_t*>(&hi);
        reinterpret_cast<uint2*>(dst)[j] = pk;
    }
}

// ---------------- embedding-bag pooling ----------------
__global__ void pool_kernel(const int* __restrict__ x, const float* __restrict__ emb,
                            __nv_bfloat16* __restrict__ pooled) {
    int b = blockIdx.x;
    int tid = threadIdx.x;
    __shared__ int xs[L_SEQ];
    if (tid < L_SEQ) xs[tid] = x[b * L_SEQ + tid];
    __syncthreads();
    float acc = 0.f;
    int cnt = 0;
    #pragma unroll
    for (int l = 0; l < L_SEQ; l++) {
        int idx = xs[l];
        if (idx != 0) {
            cnt++;
            acc += emb[(size_t)idx * EMBED + tid];
        }
    }
    float c = (float)(cnt < 1 ? 1 : cnt);
    pooled[b * EMBED + tid] = __float2bfloat16(acc / c);
}

// ---------------- GEMM body: CTA tile 128(M) x 64(N), 8 warps (4M x 2N), warp 32x32 ----------------
// MODE 0: bf16 store to outBf. MODE 1: sumexp stats (+head extras). MODE 2: add + fp32 store.
template <int K, int MODE>
__device__ __forceinline__ void gemm_body(
    const __nv_bfloat16* __restrict__ A, const __nv_bfloat16* __restrict__ W,
    int NW, int NS, float* __restrict__ out, int colOff, int group, int isHead,
    __nv_bfloat16* __restrict__ outBf, int ldOutBf,
    int m0, int n0, int tileIdx, __nv_bfloat16* smem) {
    constexpr int TS = K + 8;
    __nv_bfloat16* As = smem;             // [128][TS]
    __nv_bfloat16* Ws = smem + 128 * TS;  // [64][TS]
    __shared__ float red_s[128][2];
    __shared__ float adds_s[128];

    int tid = threadIdx.x;
    if (MODE == 2) {
        if (tid < 128) adds_s[tid] = g_adds[(m0 + tid) * 3 + group];
    }

    constexpr int kVec = K >> 3;  // uint4 chunks per row
    #pragma unroll
    for (int i = tid; i < 128 * kVec; i += 256) {
        int r = i / kVec, c = i - r * kVec;
        uint4 v = *reinterpret_cast<const uint4*>(A + (size_t)(m0 + r) * K + c * 8);
        *reinterpret_cast<uint4*>(As + r * TS + c * 8) = v;
    }
    #pragma unroll
    for (int i = tid; i < 64 * kVec; i += 256) {
        int r = i / kVec, c = i - r * kVec;
        int wr = n0 + r;
        uint4 v = make_uint4(0u, 0u, 0u, 0u);
        if (wr < NW) v = *reinterpret_cast<const uint4*>(W + (size_t)wr * K + c * 8);
        *reinterpret_cast<uint4*>(Ws + r * TS + c * 8) = v;
    }
    __syncthreads();

    int warp = tid >> 5, lane = tid & 31;
    int g = lane >> 2, t4 = lane & 3;
    int wmi = warp >> 1;  // 0..3 -> 32-row slices
    int wni = warp & 1;   // 0..1 -> 32-col slices

    uint32_t aBase[2], bBase[2];
    #pragma unroll
    for (int mt = 0; mt < 2; mt++)
        aBase[mt] = smem_u32(As + (wmi * 32 + mt * 16 + (lane & 15)) * TS + (lane >> 4) * 8);
    {
        int q = lane >> 3;
        int brow = (q >> 1) * 8 + (lane & 7);
        int bk = (q & 1) * 8;
        #pragma unroll
        for (int p = 0; p < 2; p++)
            bBase[p] = smem_u32(Ws + (wni * 32 + p * 16 + brow) * TS + bk);
    }

    float acc[2][4][4];
    #pragma unroll
    for (int mt = 0; mt < 2; mt++)
        #pragma unroll
        for (int nt = 0; nt < 4; nt++)
            #pragma unroll
            for (int i = 0; i < 4; i++) acc[mt][nt][i] = 0.f;

    #pragma unroll
    for (int k0 = 0; k0 < K; k0 += 16) {
        uint32_t a[2][4], b[2][4];
        #pragma unroll
        for (int mt = 0; mt < 2; mt++)
            asm volatile("ldmatrix.sync.aligned.m8n8.x4.shared.b16 {%0,%1,%2,%3}, [%4];"
                         : "=r"(a[mt][0]), "=r"(a[mt][1]), "=r"(a[mt][2]), "=r"(a[mt][3])
                         : "r"(aBase[mt] + k0 * 2));
        #pragma unroll
        for (int p = 0; p < 2; p++)
            asm volatile("ldmatrix.sync.aligned.m8n8.x4.shared.b16 {%0,%1,%2,%3}, [%4];"
                         : "=r"(b[p][0]), "=r"(b[p][1]), "=r"(b[p][2]), "=r"(b[p][3])
                         : "r"(bBase[p] + k0 * 2));
        #pragma unroll
        for (int mt = 0; mt < 2; mt++)
            #pragma unroll
            for (int nt = 0; nt < 4; nt++) {
                const uint32_t* bb = &b[nt >> 1][(nt & 1) * 2];
                asm volatile(
                    "mma.sync.aligned.m16n8k16.row.col.f32.bf16.bf16.f32 "
                    "{%0,%1,%2,%3}, {%4,%5,%6,%7}, {%8,%9}, {%0,%1,%2,%3};"
                    : "+f"(acc[mt][nt][0]), "+f"(acc[mt][nt][1]),
                      "+f"(acc[mt][nt][2]), "+f"(acc[mt][nt][3])
                    : "r"(a[mt][0]), "r"(a[mt][1]), "r"(a[mt][2]), "r"(a[mt][3]),
                      "r"(bb[0]), "r"(bb[1]));
            }
    }

    if (MODE == 0) {
        #pragma unroll
        for (int mt = 0; mt < 2; mt++)
            #pragma unroll
            for (int half = 0; half < 2; half++) {
                int gr = m0 + wmi * 32 + mt * 16 + g + half * 8;
                #pragma unroll
                for (int nt = 0; nt < 4; nt++)
                    #pragma unroll
                    for (int h = 0; h < 2; h++) {
                        int gc = n0 + wni * 32 + nt * 8 + t4 * 2 + h;
                        if (gc < NW)
                            outBf[(size_t)gr * ldOutBf + gc] =
                                __float2bfloat16(acc[mt][nt][half * 2 + h]);
                    }
            }
        return;
    }

    if (MODE == 1) {
        #pragma unroll
        for (int mt = 0; mt < 2; mt++) {
            #pragma unroll
            for (int half = 0; half < 2; half++) {
                int rowRel = wmi * 32 + mt * 16 + g + half * 8;
                float s = 0.f;
                #pragma unroll
                for (int nt = 0; nt < 4; nt++)
                    #pragma unroll
                    for (int h = 0; h < 2; h++) {
                        int gc = n0 + wni * 32 + nt * 8 + t4 * 2 + h;
                        float v = acc[mt][nt][half * 2 + h];
                        if (gc < NW) {
                            s += __expf(v);
                            if (isHead && gc >= CUT0)
                                g_extra[(size_t)(m0 + rowRel) * 2 + (gc - CUT0)] = v;
                        }
                    }
                s += __shfl_xor_sync(0xffffffffu, s, 1);
                s += __shfl_xor_sync(0xffffffffu, s, 2);
                if (t4 == 0) red_s[rowRel][wni] = s;
            }
        }
        __syncthreads();
        if (tid < 128) {
            float S = red_s[tid][0] + red_s[tid][1];
            g_stats_s[((size_t)group * B_ROWS + m0 + tid) * TILE_STRIDE + tileIdx] = S;
        }
        return;
    }

    // MODE 2: fused add + fp32 streaming store
    #pragma unroll
    for (int mt = 0; mt < 2; mt++)
        #pragma unroll
        for (int half = 0; half < 2; half++) {
            int rowRel = wmi * 32 + mt * 16 + g + half * 8;
            size_t gr = (size_t)(m0 + rowRel);
            float add = adds_s[rowRel];
            #pragma unroll
            for (int nt = 0; nt < 4; nt++) {
                int gc = n0 + wni * 32 + nt * 8 + t4 * 2;
                if (gc < NS) {
                    float2 w = make_float2(acc[mt][nt][half * 2 + 0] + add,
                                           acc[mt][nt][half * 2 + 1] + add);
                    __stcs(reinterpret_cast<float2*>(out + gr * OUT_LD + colOff + gc), w);
                }
            }
        }
}

// ---------------- merged kernels ----------------
__global__ void __launch_bounds__(256, 3)
stats_kernel(const __nv_bfloat16* __restrict__ pooled, const __nv_bfloat16* __restrict__ h0,
             const __nv_bfloat16* __restrict__ h1) {
    extern __shared__ __nv_bfloat16 sm[];
    int bx = blockIdx.x, m0 = blockIdx.y * 128;
    if (bx < NT_HEAD)
        gemm_body<128, 1>(pooled, g_headw, HEAD_N, 0, nullptr, 0, 0, 1, nullptr, 0,
                          m0, bx * 64, bx, sm);
    else if (bx < NT_HEAD + NT_T0)
        gemm_body<64, 1>(h0, g_t0o, CUT0, 0, nullptr, 0, 1, 0, nullptr, 0,
                         m0, (bx - NT_HEAD) * 64, bx - NT_HEAD, sm);
    else
        gemm_body<32, 1>(h1, g_t1o, N_T1, 0, nullptr, 0, 2, 0, nullptr, 0,
                         m0, (bx - NT_HEAD - NT_T0) * 64, bx - NT_HEAD - NT_T0, sm);
}

__global__ void __launch_bounds__(256, 3)
store_kernel(const __nv_bfloat16* __restrict__ pooled, const __nv_bfloat16* __restrict__ h0,
             const __nv_bfloat16* __restrict__ h1, float* __restrict__ out) {
    extern __shared__ __nv_bfloat16 sm[];
    int bx = blockIdx.x, m0 = blockIdx.y * 128;
    if (bx < NT_HEAD)
        gemm_body<128, 2>(pooled, g_headw, HEAD_N, CUT0, out, 0, 0, 1, nullptr, 0,
                          m0, bx * 64, bx, sm);
    else if (bx < NT_HEAD + NT_T0)
        gemm_body<64, 2>(h0, g_t0o, CUT0, CUT0, out, CUT0, 1, 0, nullptr, 0,
                         m0, (bx - NT_HEAD) * 64, bx - NT_HEAD, sm);
    else
        gemm_body<32, 2>(h1, g_t1o, N_T1, N_T1, out, CUT1, 2, 0, nullptr, 0,
                         m0, (bx - NT_HEAD - NT_T0) * 64, bx - NT_HEAD - NT_T0, sm);
}

__global__ void __launch_bounds__(256, 3)
proj_kernel(const __nv_bfloat16* __restrict__ pooled) {
    extern __shared__ __nv_bfloat16 sm[];
    int m0 = blockIdx.y * 128;
    if (blockIdx.x == 0)
        gemm_body<128, 0>(pooled, g_t0p, H0_DIM, 0, nullptr, 0, 0, 0, g_h0, H0_DIM,
                          m0, 0, 0, sm);
    else
        gemm_body<128, 0>(pooled, g_t1p, H1_DIM, 0, nullptr, 0, 0, 0, g_h1, H1_DIM,
                          m0, 0, 0, sm);
}

// ---------------- combine per-tile sumexp -> per-row additive constants ----------------
__global__ void combine_kernel() {
    int r = blockIdx.x * 8 + (threadIdx.x >> 5);
    int lane = threadIdx.x & 31;
    const int nT[3] = { NT_HEAD, NT_T0, NT_T1 };
    float lse[3];
    #pragma unroll
    for (int grp = 0; grp < 3; grp++) {
        const float* ps = g_stats_s + ((size_t)grp * B_ROWS + r) * TILE_STRIDE;
        float s = 0.f;
        for (int t = lane; t < nT[grp]; t += 32) s += ps[t];
        #pragma unroll
        for (int off = 16; off > 0; off >>= 1)
            s += __shfl_xor_sync(0xffffffffu, s, off);
        lse[grp] = logf(s);
    }
    if (lane == 0) {
        float lh = lse[0];
        g_adds[r * 3 + 0] = -lh;
        g_adds[r * 3 + 1] = g_extra[r * 2 + 0] - lh - lse[1];
        g_adds[r * 3 + 2] = g_extra[r * 2 + 1] - lh - lse[2];
    }
}

// ---------------- launch ----------------
extern "C" void kernel_launch(void* const* d_in, const int* in_sizes, int n_in,
                              void* d_out, int out_size) {
    const int*   x        = (const int*)d_in[0];
    const float* emb      = (const float*)d_in[1];
    const float* head_w_f = (const float*)d_in[2];
    const float* t0p_f    = (const float*)d_in[3];
    const float* t0o_f    = (const float*)d_in[4];
    const float* t1p_f    = (const float*)d_in[5];
    const float* t1o_f    = (const float*)d_in[6];
    float* out = (float*)d_out;

    __nv_bfloat16 *p_pooled, *p_h0, *p_h1;
    cudaGetSymbolAddress((void**)&p_pooled, g_pooled);
    cudaGetSymbolAddress((void**)&p_h0, g_h0);
    cudaGetSymbolAddress((void**)&p_h1, g_h1);

    const int SMB = (128 + 64) * (128 + 8) * (int)sizeof(__nv_bfloat16);  // 52224
    cudaFuncSetAttribute(stats_kernel, cudaFuncAttributeMaxDynamicSharedMemorySize, SMB);
    cudaFuncSetAttribute(store_kernel, cudaFuncAttributeMaxDynamicSharedMemorySize, SMB);
    cudaFuncSetAttribute(proj_kernel, cudaFuncAttributeMaxDynamicSharedMemorySize, SMB);

    // weight converts (one launch)
    cvt_all<<<784, 256>>>(head_w_f, t0o_f, t1o_f, t0p_f, t1p_f);
    // pooling
    pool_kernel<<<B_ROWS, 128>>>(x, emb, p_pooled);
    // projections (h0, h1)
    proj_kernel<<<dim3(2, 16), 256, SMB>>>(p_pooled);
    // pass A: sum-exp stats for all three groups
    stats_kernel<<<dim3(NT_HEAD + NT_T0 + NT_T1, 16), 256, SMB>>>(p_pooled, p_h0, p_h1);
    // combine -> per-row additive constants
    combine_kernel<<<B_ROWS / 8, 256>>>();
    // pass B: recompute + fused add + single store of the 410MB output
    store_kernel<<<dim3(NT_HEAD + NT_T0 + NT_T1, 16), 256, SMB>>>(p_pooled, p_h0, p_h1, out);
}

// round 4
// speedup vs baseline: 2.1163x; 1.2280x over previous
#include <cuda_runtime.h>
#include <cuda_bf16.h>
#include <cstdint>

#define B_ROWS 2048
#define L_SEQ 50
#define EMBED 128
#define OUT_LD 50000
#define CUT0 12500
#define CUT1 25000
#define HEAD_N 12502
#define H0_DIM 64
#define H1_DIM 32
#define N_T1 25000
#define TILE_STRIDE 400

#define LOG2E 1.4426950408889634f
#define LN2   0.6931471805599453f

// ---------------- scratch (static device memory; no allocations) ----------------
__device__ __align__(16) __nv_bfloat16 g_pooled[B_ROWS * EMBED];
__device__ __align__(16) __nv_bfloat16 g_pooledS[B_ROWS * EMBED];   // * log2(e)
__device__ __align__(16) __nv_bfloat16 g_headw[HEAD_N * EMBED];
__device__ __align__(16) __nv_bfloat16 g_t0o[CUT0 * H0_DIM];
__device__ __align__(16) __nv_bfloat16 g_t1o[N_T1 * H1_DIM];
__device__ __align__(16) __nv_bfloat16 g_t0p[H0_DIM * EMBED];
__device__ __align__(16) __nv_bfloat16 g_t1p[H1_DIM * EMBED];
__device__ __align__(16) __nv_bfloat16 g_h0[B_ROWS * H0_DIM];
__device__ __align__(16) __nv_bfloat16 g_h0S[B_ROWS * H0_DIM];
__device__ __align__(16) __nv_bfloat16 g_h1[B_ROWS * H1_DIM];
__device__ __align__(16) __nv_bfloat16 g_h1S[B_ROWS * H1_DIM];
__device__ float g_stats_s[3 * B_ROWS * TILE_STRIDE];
__device__ float g_extra[B_ROWS * 2];
__device__ float g_adds[B_ROWS * 3];

__device__ __forceinline__ uint32_t smem_u32(const void* p) {
    return (uint32_t)__cvta_generic_to_shared(p);
}
__device__ __forceinline__ float ex2f(float x) {
    float r; asm("ex2.approx.f32 %0, %1;" : "=f"(r) : "f"(x)); return r;
}
__device__ __forceinline__ float2 addf2(float2 a, float2 b) {
    union U { float2 f; unsigned long long u; } ua, ub, ur;
    ua.f = a; ub.f = b;
    asm("add.rn.f32x2 %0, %1, %2;" : "=l"(ur.u) : "l"(ua.u), "l"(ub.u));
    return ur.f;
}

// ---------------- prep: pooling (blocks 0..1023) + weight cvt (blocks 1024..) ----------------
#define POOL_BLOCKS 1024
#define CVT_BLOCKS 640
#define NV_H  400064u
#define NV_0  200000u
#define NV_1  200000u
#define NV_P0 2048u
#define NV_P1 1024u
__global__ void __launch_bounds__(256)
prep_kernel(const int* __restrict__ x, const float* __restrict__ emb,
            const float* __restrict__ wh, const float* __restrict__ w0,
            const float* __restrict__ w1, const float* __restrict__ p0,
            const float* __restrict__ p1) {
    int tid = threadIdx.x;
    if (blockIdx.x < POOL_BLOCKS) {
        __shared__ int xs[2 * L_SEQ];
        int base = blockIdx.x * 2;
        if (tid < 2 * L_SEQ) xs[tid] = x[base * L_SEQ + tid];
        __syncthreads();
        int row = tid >> 7;
        int dim = tid & 127;
        float acc = 0.f; int cnt = 0;
        #pragma unroll
        for (int l = 0; l < L_SEQ; l++) {
            int idx = xs[row * L_SEQ + l];
            if (idx != 0) { cnt++; acc += emb[(size_t)idx * EMBED + dim]; }
        }
        float c = (float)(cnt < 1 ? 1 : cnt);
        float v = acc / c;
        int b = base + row;
        g_pooled[b * EMBED + dim] = __float2bfloat16(v);
        g_pooledS[b * EMBED + dim] = __float2bfloat16(v * LOG2E);
    } else {
        const unsigned total = NV_H + NV_0 + NV_1 + NV_P0 + NV_P1;
        for (unsigned i = (blockIdx.x - POOL_BLOCKS) * 256u + tid; i < total;
             i += CVT_BLOCKS * 256u) {
            const float* src; __nv_bfloat16* dst; unsigned j = i;
            if (j < NV_H) { src = wh; dst = g_headw; }
            else if ((j -= NV_H) < NV_0) { src = w0; dst = g_t0o; }
            else if ((j -= NV_0) < NV_1) { src = w1; dst = g_t1o; }
            else if ((j -= NV_1) < NV_P0) { src = p0; dst = g_t0p; }
            else { j -= NV_P0; src = p1; dst = g_t1p; }
            float4 v = reinterpret_cast<const float4*>(src)[j];
            __nv_bfloat162 lo = __float22bfloat162_rn(make_float2(v.x, v.y));
            __nv_bfloat162 hi = __float22bfloat162_rn(make_float2(v.z, v.w));
            uint2 pk;
            pk.x = *reinterpret_cast<uint32_t*>(&lo);
            pk.y = *reinterpret_cast<uint32_t*>(&hi);
            reinterpret_cast<uint2*>(dst)[j] = pk;
        }
    }
}

// ---------------- multi-tile GEMM body ----------------
// CTA: A tile 128(M) x K, loops over NSUB 64-col W tiles. 8 warps, warp tile 32x32.
// MODE 0: bf16 store (+scaled copy). MODE 1: sumexp stats via ex2 (A pre-scaled by log2e).
// MODE 2: logit + per-row add -> fp32 streaming store.
template <int K, int MODE, int NSUB>
__device__ __forceinline__ void gemm_multi(
    const __nv_bfloat16* __restrict__ A, const __nv_bfloat16* __restrict__ W,
    int NW, int NS, float* __restrict__ out, int colOff, int group, int isHead,
    __nv_bfloat16* __restrict__ outBf, __nv_bfloat16* __restrict__ outBfS, int ldOutBf,
    int m0, int n0base, __nv_bfloat16* smem) {
    constexpr int TS = K + 8;
    __nv_bfloat16* As = smem;             // [128][TS]
    __nv_bfloat16* Ws = smem + 128 * TS;  // [64][TS]
    __shared__ float red_s[128][2];
    __shared__ float adds_s[128];

    int tid = threadIdx.x;
    if (MODE == 2) {
        if (tid < 128) adds_s[tid] = g_adds[(m0 + tid) * 3 + group];
    }

    constexpr int kVec = K >> 3;
    #pragma unroll
    for (int i = tid; i < 128 * kVec; i += 256) {
        int r = i / kVec, c = i - r * kVec;
        uint4 v = *reinterpret_cast<const uint4*>(A + (size_t)(m0 + r) * K + c * 8);
        *reinterpret_cast<uint4*>(As + r * TS + c * 8) = v;
    }

    int warp = tid >> 5, lane = tid & 31;
    int g = lane >> 2, t4 = lane & 3;
    int wmi = warp >> 1;
    int wni = warp & 1;

    uint32_t aBase[2], bBase[2];
    #pragma unroll
    for (int mt = 0; mt < 2; mt++)
        aBase[mt] = smem_u32(As + (wmi * 32 + mt * 16 + (lane & 15)) * TS + (lane >> 4) * 8);
    {
        int q = lane >> 3;
        int brow = (q >> 1) * 8 + (lane & 7);
        int bk = (q & 1) * 8;
        #pragma unroll
        for (int p = 0; p < 2; p++)
            bBase[p] = smem_u32(Ws + (wni * 32 + p * 16 + brow) * TS + bk);
    }

    #pragma unroll
    for (int s = 0; s < NSUB; s++) {
        int n0 = n0base + s * 64;
        if (NSUB > 1 && n0 >= NW) break;
        if (s > 0) __syncthreads();   // protect Ws from prior readers
        #pragma unroll
        for (int i = tid; i < 64 * kVec; i += 256) {
            int r = i / kVec, c = i - r * kVec;
            int wr = n0 + r;
            uint4 v = make_uint4(0u, 0u, 0u, 0u);
            if (wr < NW) v = *reinterpret_cast<const uint4*>(W + (size_t)wr * K + c * 8);
            *reinterpret_cast<uint4*>(Ws + r * TS + c * 8) = v;
        }
        __syncthreads();

        float acc[2][4][4];
        #pragma unroll
        for (int mt = 0; mt < 2; mt++)
            #pragma unroll
            for (int nt = 0; nt < 4; nt++)
                #pragma unroll
                for (int i = 0; i < 4; i++) acc[mt][nt][i] = 0.f;

        #pragma unroll
        for (int k0 = 0; k0 < K; k0 += 16) {
            uint32_t a[2][4], b[2][4];
            #pragma unroll
            for (int mt = 0; mt < 2; mt++)
                asm volatile("ldmatrix.sync.aligned.m8n8.x4.shared.b16 {%0,%1,%2,%3}, [%4];"
                             : "=r"(a[mt][0]), "=r"(a[mt][1]), "=r"(a[mt][2]), "=r"(a[mt][3])
                             : "r"(aBase[mt] + k0 * 2));
            #pragma unroll
            for (int p = 0; p < 2; p++)
                asm volatile("ldmatrix.sync.aligned.m8n8.x4.shared.b16 {%0,%1,%2,%3}, [%4];"
                             : "=r"(b[p][0]), "=r"(b[p][1]), "=r"(b[p][2]), "=r"(b[p][3])
                             : "r"(bBase[p] + k0 * 2));
            #pragma unroll
            for (int mt = 0; mt < 2; mt++)
                #pragma unroll
                for (int nt = 0; nt < 4; nt++) {
                    const uint32_t* bb = &b[nt >> 1][(nt & 1) * 2];
                    asm volatile(
                        "mma.sync.aligned.m16n8k16.row.col.f32.bf16.bf16.f32 "
                        "{%0,%1,%2,%3}, {%4,%5,%6,%7}, {%8,%9}, {%0,%1,%2,%3};"
                        : "+f"(acc[mt][nt][0]), "+f"(acc[mt][nt][1]),
                          "+f"(acc[mt][nt][2]), "+f"(acc[mt][nt][3])
                        : "r"(a[mt][0]), "r"(a[mt][1]), "r"(a[mt][2]), "r"(a[mt][3]),
                          "r"(bb[0]), "r"(bb[1]));
                }
        }

        if (MODE == 0) {
            #pragma unroll
            for (int mt = 0; mt < 2; mt++)
                #pragma unroll
                for (int half = 0; half < 2; half++) {
                    int gr = m0 + wmi * 32 + mt * 16 + g + half * 8;
                    #pragma unroll
                    for (int nt = 0; nt < 4; nt++)
                        #pragma unroll
                        for (int h = 0; h < 2; h++) {
                            int gc = n0 + wni * 32 + nt * 8 + t4 * 2 + h;
                            if (gc < NW) {
                                float v = acc[mt][nt][half * 2 + h];
                                outBf[(size_t)gr * ldOutBf + gc] = __float2bfloat16(v);
                                outBfS[(size_t)gr * ldOutBf + gc] = __float2bfloat16(v * LOG2E);
                            }
                        }
                }
        } else if (MODE == 1) {
            bool full = (n0 + 64 <= NW);
            #pragma unroll
            for (int mt = 0; mt < 2; mt++) {
                #pragma unroll
                for (int half = 0; half < 2; half++) {
                    int rowRel = wmi * 32 + mt * 16 + g + half * 8;
                    float ssum = 0.f;
                    if (full) {
                        #pragma unroll
                        for (int nt = 0; nt < 4; nt++) {
                            ssum += ex2f(acc[nt >> 1][((nt & 1) << 1) | 0][half * 2 + 0] * 0.f +
                                         acc[mt][nt][half * 2 + 0]);
                            ssum += ex2f(acc[mt][nt][half * 2 + 1]);
                        }
                    } else {
                        #pragma unroll
                        for (int nt = 0; nt < 4; nt++)
                            #pragma unroll
                            for (int h = 0; h < 2; h++) {
                                int gc = n0 + wni * 32 + nt * 8 + t4 * 2 + h;
                                float v = acc[mt][nt][half * 2 + h];
                                if (gc < NW) {
                                    ssum += ex2f(v);
                                    if (isHead && gc >= CUT0)
                                        g_extra[(size_t)(m0 + rowRel) * 2 + (gc - CUT0)] = v;
                                }
                            }
                    }
                    ssum += __shfl_xor_sync(0xffffffffu, ssum, 1);
                    ssum += __shfl_xor_sync(0xffffffffu, ssum, 2);
                    if (t4 == 0) red_s[rowRel][wni] = ssum;
                }
            }
            __syncthreads();
            if (tid < 128) {
                float S = red_s[tid][0] + red_s[tid][1];
                g_stats_s[((size_t)group * B_ROWS + m0 + tid) * TILE_STRIDE + (n0 >> 6)] = S;
            }
        } else {
            bool full = (n0 + 64 <= NS);
            #pragma unroll
            for (int mt = 0; mt < 2; mt++)
                #pragma unroll
                for (int half = 0; half < 2; half++) {
                    int rowRel = wmi * 32 + mt * 16 + g + half * 8;
                    size_t gr = (size_t)(m0 + rowRel);
                    float add = adds_s[rowRel];
                    float2 addv = make_float2(add, add);
                    float* rowp = out + gr * OUT_LD + colOff;
                    if (full) {
                        #pragma unroll
                        for (int nt = 0; nt < 4; nt++) {
                            int gc = n0 + wni * 32 + nt * 8 + t4 * 2;
                            float2 w = addf2(make_float2(acc[mt][nt][half * 2 + 0],
                                                         acc[mt][nt][half * 2 + 1]), addv);
                            __stcs(reinterpret_cast<float2*>(rowp + gc), w);
                        }
                    } else {
                        #pragma unroll
                        for (int nt = 0; nt < 4; nt++) {
                            int gc = n0 + wni * 32 + nt * 8 + t4 * 2;
                            if (gc < NS) {
                                float2 w = addf2(make_float2(acc[mt][nt][half * 2 + 0],
                                                             acc[mt][nt][half * 2 + 1]), addv);
                                __stcs(reinterpret_cast<float2*>(rowp + gc), w);
                            }
                        }
                    }
                }
        }
    }
}

// ---------------- kernels ----------------
__global__ void __launch_bounds__(256, 3)
proj_kernel() {
    extern __shared__ __nv_bfloat16 sm[];
    int m0 = blockIdx.y * 128;
    if (blockIdx.x == 0)
        gemm_multi<128, 0, 1>(g_pooled, g_t0p, H0_DIM, 0, nullptr, 0, 0, 0,
                              g_h0, g_h0S, H0_DIM, m0, 0, sm);
    else
        gemm_multi<128, 0, 1>(g_pooled, g_t1p, H1_DIM, 0, nullptr, 0, 0, 0,
                              g_h1, g_h1S, H1_DIM, m0, 0, sm);
}

__global__ void __launch_bounds__(256, 3)
stats_kernel() {
    extern __shared__ __nv_bfloat16 sm[];
    int bx = blockIdx.x, m0 = blockIdx.y * 128;
    if (bx < 98)
        gemm_multi<128, 1, 2>(g_pooledS, g_headw, HEAD_N, 0, nullptr, 0, 0, 1,
                              nullptr, nullptr, 0, m0, bx * 128, sm);
    else if (bx < 196)
        gemm_multi<64, 1, 2>(g_h0S, g_t0o, CUT0, 0, nullptr, 0, 1, 0,
                             nullptr, nullptr, 0, m0, (bx - 98) * 128, sm);
    else
        gemm_multi<32, 1, 4>(g_h1S, g_t1o, N_T1, 0, nullptr, 0, 2, 0,
                             nullptr, nullptr, 0, m0, (bx - 196) * 256, sm);
}

__global__ void __launch_bounds__(256, 3)
store_kernel(float* __restrict__ out) {
    extern __shared__ __nv_bfloat16 sm[];
    int bx = blockIdx.x, m0 = blockIdx.y * 128;
    if (bx < 98)
        gemm_multi<128, 2, 2>(g_pooled, g_headw, HEAD_N, CUT0, out, 0, 0, 1,
                              nullptr, nullptr, 0, m0, bx * 128, sm);
    else if (bx < 196)
        gemm_multi<64, 2, 2>(g_h0, g_t0o, CUT0, CUT0, out, CUT0, 1, 0,
                             nullptr, nullptr, 0, m0, (bx - 98) * 128, sm);
    else
        gemm_multi<32, 2, 4>(g_h1, g_t1o, N_T1, N_T1, out, CUT1, 2, 0,
                             nullptr, nullptr, 0, m0, (bx - 196) * 256, sm);
}

// ---------------- combine per-tile sumexp -> per-row additive constants ----------------
__global__ void combine_kernel() {
    int r = blockIdx.x * 8 + (threadIdx.x >> 5);
    int lane = threadIdx.x & 31;
    const int nT[3] = { 196, 196, 391 };
    float lse[3];
    #pragma unroll
    for (int grp = 0; grp < 3; grp++) {
        const float* ps = g_stats_s + ((size_t)grp * B_ROWS + r) * TILE_STRIDE;
        float s = 0.f;
        for (int t = lane; t < nT[grp]; t += 32) s += ps[t];
        #pragma unroll
        for (int off = 16; off > 0; off >>= 1)
            s += __shfl_xor_sync(0xffffffffu, s, off);
        lse[grp] = logf(s);
    }
    if (lane == 0) {
        float lh = lse[0];
        g_adds[r * 3 + 0] = -lh;
        g_adds[r * 3 + 1] = g_extra[r * 2 + 0] * LN2 - lh - lse[1];
        g_adds[r * 3 + 2] = g_extra[r * 2 + 1] * LN2 - lh - lse[2];
    }
}

// ---------------- launch ----------------
extern "C" void kernel_launch(void* const* d_in, const int* in_sizes, int n_in,
                              void* d_out, int out_size) {
    const int*   x        = (const int*)d_in[0];
    const float* emb      = (const float*)d_in[1];
    const float* head_w_f = (const float*)d_in[2];
    const float* t0p_f    = (const float*)d_in[3];
    const float* t0o_f    = (const float*)d_in[4];
    const float* t1p_f    = (const float*)d_in[5];
    const float* t1o_f    = (const float*)d_in[6];
    float* out = (float*)d_out;

    const int SMB = (128 + 64) * (128 + 8) * (int)sizeof(__nv_bfloat16);  // 52224
    cudaFuncSetAttribute(stats_kernel, cudaFuncAttributeMaxDynamicSharedMemorySize, SMB);
    cudaFuncSetAttribute(store_kernel, cudaFuncAttributeMaxDynamicSharedMemorySize, SMB);
    cudaFuncSetAttribute(proj_kernel, cudaFuncAttributeMaxDynamicSharedMemorySize, SMB);

    prep_kernel<<<POOL_BLOCKS + CVT_BLOCKS, 256>>>(x, emb, head_w_f, t0o_f, t1o_f,
                                                   t0p_f, t1p_f);
    proj_kernel<<<dim3(2, 16), 256, SMB>>>();
    stats_kernel<<<dim3(294, 16), 256, SMB>>>();
    combine_kernel<<<B_ROWS / 8, 256>>>();
    store_kernel<<<dim3(294, 16), 256, SMB>>>(out);
}

// round 5
// speedup vs baseline: 2.1581x; 1.0197x over previous
#include <cuda_runtime.h>
#include <cuda_bf16.h>
#include <cstdint>

#define B_ROWS 2048
#define L_SEQ 50
#define EMBED 128
#define OUT_LD 50000
#define CUT0 12500
#define CUT1 25000
#define HEAD_N 12502
#define H0_DIM 64
#define H1_DIM 32
#define N_T1 25000
#define TILE_STRIDE 400

#define LOG2E 1.4426950408889634f
#define LN2   0.6931471805599453f

// ---------------- scratch (static device memory; no allocations) ----------------
__device__ __align__(16) __nv_bfloat16 g_pooled[B_ROWS * EMBED];
__device__ __align__(16) __nv_bfloat16 g_pooledS[B_ROWS * EMBED];   // * log2(e)
__device__ __align__(16) __nv_bfloat16 g_headw[HEAD_N * EMBED];
__device__ __align__(16) __nv_bfloat16 g_t0o[CUT0 * H0_DIM];
__device__ __align__(16) __nv_bfloat16 g_t1o[N_T1 * H1_DIM];
__device__ __align__(16) __nv_bfloat16 g_t0p[H0_DIM * EMBED];
__device__ __align__(16) __nv_bfloat16 g_t1p[H1_DIM * EMBED];
__device__ __align__(16) __nv_bfloat16 g_h0[B_ROWS * H0_DIM];
__device__ __align__(16) __nv_bfloat16 g_h0S[B_ROWS * H0_DIM];
__device__ __align__(16) __nv_bfloat16 g_h1[B_ROWS * H1_DIM];
__device__ __align__(16) __nv_bfloat16 g_h1S[B_ROWS * H1_DIM];
__device__ float g_stats_s[3 * B_ROWS * TILE_STRIDE];
__device__ float g_extra[B_ROWS * 2];
__device__ float g_adds[B_ROWS * 3];

__device__ __forceinline__ uint32_t smem_u32(const void* p) {
    return (uint32_t)__cvta_generic_to_shared(p);
}
__device__ __forceinline__ float ex2f(float x) {
    float r; asm("ex2.approx.f32 %0, %1;" : "=f"(r) : "f"(x)); return r;
}
__device__ __forceinline__ float2 addf2(float2 a, float2 b) {
    union U { float2 f; unsigned long long u; } ua, ub, ur;
    ua.f = a; ub.f = b;
    asm("add.rn.f32x2 %0, %1, %2;" : "=l"(ur.u) : "l"(ua.u), "l"(ub.u));
    return ur.f;
}
__device__ __forceinline__ void cp16(uint32_t dst, const void* src, int sz) {
    asm volatile("cp.async.cg.shared.global [%0], [%1], 16, %2;"
                 :: "r"(dst), "l"(src), "r"(sz) : "memory");
}
#define CP_COMMIT() asm volatile("cp.async.commit_group;" ::: "memory")
#define CP_WAIT(n)  asm volatile("cp.async.wait_group %0;" :: "n"(n) : "memory")

// ---------------- prep: pooling (blocks 0..1023) + weight cvt ----------------
#define POOL_BLOCKS 1024
#define CVT_BLOCKS 640
#define NV_H  400064u
#define NV_0  200000u
#define NV_1  200000u
#define NV_P0 2048u
#define NV_P1 1024u
__global__ void __launch_bounds__(256)
prep_kernel(const int* __restrict__ x, const float* __restrict__ emb,
            const float* __restrict__ wh, const float* __restrict__ w0,
            const float* __restrict__ w1, const float* __restrict__ p0,
            const float* __restrict__ p1) {
    int tid = threadIdx.x;
    if (blockIdx.x < POOL_BLOCKS) {
        __shared__ int xs[2 * L_SEQ];
        int base = blockIdx.x * 2;
        if (tid < 2 * L_SEQ) xs[tid] = x[base * L_SEQ + tid];
        __syncthreads();
        int row = tid >> 7;
        int dim = tid & 127;
        float acc = 0.f; int cnt = 0;
        #pragma unroll
        for (int l = 0; l < L_SEQ; l++) {
            int idx = xs[row * L_SEQ + l];
            if (idx != 0) { cnt++; acc += emb[(size_t)idx * EMBED + dim]; }
        }
        float c = (float)(cnt < 1 ? 1 : cnt);
        float v = acc / c;
        int b = base + row;
        g_pooled[b * EMBED + dim] = __float2bfloat16(v);
        g_pooledS[b * EMBED + dim] = __float2bfloat16(v * LOG2E);
    } else {
        const unsigned total = NV_H + NV_0 + NV_1 + NV_P0 + NV_P1;
        for (unsigned i = (blockIdx.x - POOL_BLOCKS) * 256u + tid; i < total;
             i += CVT_BLOCKS * 256u) {
            const float* src; __nv_bfloat16* dst; unsigned j = i;
            if (j < NV_H) { src = wh; dst = g_headw; }
            else if ((j -= NV_H) < NV_0) { src = w0; dst = g_t0o; }
            else if ((j -= NV_0) < NV_1) { src = w1; dst = g_t1o; }
            else if ((j -= NV_1) < NV_P0) { src = p0; dst = g_t0p; }
            else { j -= NV_P0; src = p1; dst = g_t1p; }
            float4 v = reinterpret_cast<const float4*>(src)[j];
            __nv_bfloat162 lo = __float22bfloat162_rn(make_float2(v.x, v.y));
            __nv_bfloat162 hi = __float22bfloat162_rn(make_float2(v.z, v.w));
            uint2 pk;
            pk.x = *reinterpret_cast<uint32_t*>(&lo);
            pk.y = *reinterpret_cast<uint32_t*>(&hi);
            reinterpret_cast<uint2*>(dst)[j] = pk;
        }
    }
}

// ---------------- multi-tile GEMM body, cp.async double-buffered W ----------------
// CTA: A tile 128(M) x K, loops over NSUB 64-col W tiles. 8 warps, warp tile 32x32.
template <int K, int MODE, int NSUB>
__device__ __forceinline__ void gemm_multi(
    const __nv_bfloat16* __restrict__ A, const __nv_bfloat16* __restrict__ W,
    int NW, int NS, float* __restrict__ out, int colOff, int group, int isHead,
    __nv_bfloat16* __restrict__ outBf, __nv_bfloat16* __restrict__ outBfS, int ldOutBf,
    int m0, int n0base, __nv_bfloat16* smem) {
    constexpr int TS = K + 8;
    constexpr int CW = K >> 3;   // 16B chunks per row
    __nv_bfloat16* As = smem;                         // [128][TS]
    __nv_bfloat16* W0 = smem + 128 * TS;              // [64][TS] buf0
    const int WBUF_BYTES = 64 * TS * 2;
    __shared__ float red_s[128][2];
    __shared__ float adds_s[128];

    int tid = threadIdx.x;
    if (MODE == 2) {
        if (tid < 128) adds_s[tid] = g_adds[(m0 + tid) * 3 + group];
    }

    // A fill (cp.async)
    #pragma unroll
    for (int i = tid; i < 128 * CW; i += 256) {
        int r = i / CW, c = i - r * CW;
        cp16(smem_u32(As + r * TS + c * 8), A + (size_t)(m0 + r) * K + c * 8, 16);
    }
    // W tile 0 fill (cp.async, zero-fill OOB)
    {
        __nv_bfloat16* wb = W0;
        #pragma unroll
        for (int i = tid; i < 64 * CW; i += 256) {
            int r = i / CW, c = i - r * CW;
            int wr = n0base + r;
            int wrc = wr < NW ? wr : (NW - 1);
            cp16(smem_u32(wb + r * TS + c * 8),
                 W + (size_t)wrc * K + c * 8, wr < NW ? 16 : 0);
        }
    }
    CP_COMMIT();

    int warp = tid >> 5, lane = tid & 31;
    int g = lane >> 2, t4 = lane & 3;
    int wmi = warp >> 1;
    int wni = warp & 1;

    uint32_t aBase[2], bBase0[2];
    #pragma unroll
    for (int mt = 0; mt < 2; mt++)
        aBase[mt] = smem_u32(As + (wmi * 32 + mt * 16 + (lane & 15)) * TS + (lane >> 4) * 8);
    {
        int q = lane >> 3;
        int brow = (q >> 1) * 8 + (lane & 7);
        int bk = (q & 1) * 8;
        #pragma unroll
        for (int p = 0; p < 2; p++)
            bBase0[p] = smem_u32(W0 + (wni * 32 + p * 16 + brow) * TS + bk);
    }

    #pragma unroll
    for (int s = 0; s < NSUB; s++) {
        int n0 = n0base + s * 64;
        if (NSUB > 1 && n0 >= NW) break;
        bool havenext = (s + 1 < NSUB) && (n0 + 64 < NW || NSUB == 1);
        if (s + 1 < NSUB && n0base + (s + 1) * 64 < NW) {
            havenext = true;
            int n1 = n0 + 64;
            __nv_bfloat16* wb = W0 + ((s + 1) & 1) * (64 * TS);
            #pragma unroll
            for (int i = tid; i < 64 * CW; i += 256) {
                int r = i / CW, c = i - r * CW;
                int wr = n1 + r;
                int wrc = wr < NW ? wr : (NW - 1);
                cp16(smem_u32(wb + r * TS + c * 8),
                     W + (size_t)wrc * K + c * 8, wr < NW ? 16 : 0);
            }
            CP_COMMIT();
            CP_WAIT(1);
        } else {
            havenext = false;
            CP_WAIT(0);
        }
        __syncthreads();

        uint32_t bOff = (uint32_t)((s & 1) * WBUF_BYTES);
        float acc[2][4][4];
        #pragma unroll
        for (int mt = 0; mt < 2; mt++)
            #pragma unroll
            for (int nt = 0; nt < 4; nt++)
                #pragma unroll
                for (int i = 0; i < 4; i++) acc[mt][nt][i] = 0.f;

        #pragma unroll
        for (int k0 = 0; k0 < K; k0 += 16) {
            uint32_t a[2][4], b[2][4];
            #pragma unroll
            for (int mt = 0; mt < 2; mt++)
                asm volatile("ldmatrix.sync.aligned.m8n8.x4.shared.b16 {%0,%1,%2,%3}, [%4];"
                             : "=r"(a[mt][0]), "=r"(a[mt][1]), "=r"(a[mt][2]), "=r"(a[mt][3])
                             : "r"(aBase[mt] + k0 * 2));
            #pragma unroll
            for (int p = 0; p < 2; p++)
                asm volatile("ldmatrix.sync.aligned.m8n8.x4.shared.b16 {%0,%1,%2,%3}, [%4];"
                             : "=r"(b[p][0]), "=r"(b[p][1]), "=r"(b[p][2]), "=r"(b[p][3])
                             : "r"(bBase0[p] + bOff + k0 * 2));
            #pragma unroll
            for (int mt = 0; mt < 2; mt++)
                #pragma unroll
                for (int nt = 0; nt < 4; nt++) {
                    const uint32_t* bb = &b[nt >> 1][(nt & 1) * 2];
                    asm volatile(
                        "mma.sync.aligned.m16n8k16.row.col.f32.bf16.bf16.f32 "
                        "{%0,%1,%2,%3}, {%4,%5,%6,%7}, {%8,%9}, {%0,%1,%2,%3};"
                        : "+f"(acc[mt][nt][0]), "+f"(acc[mt][nt][1]),
                          "+f"(acc[mt][nt][2]), "+f"(acc[mt][nt][3])
                        : "r"(a[mt][0]), "r"(a[mt][1]), "r"(a[mt][2]), "r"(a[mt][3]),
                          "r"(bb[0]), "r"(bb[1]));
                }
        }

        if (MODE == 0) {
            #pragma unroll
            for (int mt = 0; mt < 2; mt++)
                #pragma unroll
                for (int half = 0; half < 2; half++) {
                    int gr = m0 + wmi * 32 + mt * 16 + g + half * 8;
                    #pragma unroll
                    for (int nt = 0; nt < 4; nt++)
                        #pragma unroll
                        for (int h = 0; h < 2; h++) {
                            int gc = n0 + wni * 32 + nt * 8 + t4 * 2 + h;
                            if (gc < NW) {
                                float v = acc[mt][nt][half * 2 + h];
                                outBf[(size_t)gr * ldOutBf + gc] = __float2bfloat16(v);
                                outBfS[(size_t)gr * ldOutBf + gc] = __float2bfloat16(v * LOG2E);
                            }
                        }
                }
            if (havenext) __syncthreads();
        } else if (MODE == 1) {
            bool full = (n0 + 64 <= NW);
            #pragma unroll
            for (int mt = 0; mt < 2; mt++) {
                #pragma unroll
                for (int half = 0; half < 2; half++) {
                    int rowRel = wmi * 32 + mt * 16 + g + half * 8;
                    float ssum = 0.f;
                    if (full) {
                        #pragma unroll
                        for (int nt = 0; nt < 4; nt++) {
                            ssum += ex2f(acc[mt][nt][half * 2 + 0]);
                            ssum += ex2f(acc[mt][nt][half * 2 + 1]);
                        }
                    } else {
                        #pragma unroll
                        for (int nt = 0; nt < 4; nt++)
                            #pragma unroll
                            for (int h = 0; h < 2; h++) {
                                int gc = n0 + wni * 32 + nt * 8 + t4 * 2 + h;
                                float v = acc[mt][nt][half * 2 + h];
                                if (gc < NW) {
                                    ssum += ex2f(v);
                                    if (isHead && gc >= CUT0)
                                        g_extra[(size_t)(m0 + rowRel) * 2 + (gc - CUT0)] = v;
                                }
                            }
                    }
                    ssum += __shfl_xor_sync(0xffffffffu, ssum, 1);
                    ssum += __shfl_xor_sync(0xffffffffu, ssum, 2);
                    if (t4 == 0) red_s[rowRel][wni] = ssum;
                }
            }
            __syncthreads();
            if (tid < 128) {
                float S = red_s[tid][0] + red_s[tid][1];
                g_stats_s[((size_t)group * B_ROWS + m0 + tid) * TILE_STRIDE + (n0 >> 6)] = S;
            }
        } else {
            bool full = (n0 + 64 <= NS);
            #pragma unroll
            for (int mt = 0; mt < 2; mt++)
                #pragma unroll
                for (int half = 0; half < 2; half++) {
                    int rowRel = wmi * 32 + mt * 16 + g + half * 8;
                    size_t gr = (size_t)(m0 + rowRel);
                    float add = adds_s[rowRel];
                    float2 addv = make_float2(add, add);
                    float* rowp = out + gr * OUT_LD + colOff;
                    if (full) {
                        #pragma unroll
                        for (int nt = 0; nt < 4; nt++) {
                            int gc = n0 + wni * 32 + nt * 8 + t4 * 2;
                            float2 w = addf2(make_float2(acc[mt][nt][half * 2 + 0],
                                                         acc[mt][nt][half * 2 + 1]), addv);
                            __stcs(reinterpret_cast<float2*>(rowp + gc), w);
                        }
                    } else {
                        #pragma unroll
                        for (int nt = 0; nt < 4; nt++) {
                            int gc = n0 + wni * 32 + nt * 8 + t4 * 2;
                            if (gc < NS) {
                                float2 w = addf2(make_float2(acc[mt][nt][half * 2 + 0],
                                                             acc[mt][nt][half * 2 + 1]), addv);
                                __stcs(reinterpret_cast<float2*>(rowp + gc), w);
                            }
                        }
                    }
                }
            if (havenext) __syncthreads();
        }
    }
}

// ---------------- kernels ----------------
__global__ void __launch_bounds__(256, 3)
proj_kernel() {
    extern __shared__ __nv_bfloat16 sm[];
    int m0 = blockIdx.y * 128;
    if (blockIdx.x == 0)
        gemm_multi<128, 0, 1>(g_pooled, g_t0p, H0_DIM, 0, nullptr, 0, 0, 0,
                              g_h0, g_h0S, H0_DIM, m0, 0, sm);
    else
        gemm_multi<128, 0, 1>(g_pooled, g_t1p, H1_DIM, 0, nullptr, 0, 0, 0,
                              g_h1, g_h1S, H1_DIM, m0, 0, sm);
}

__global__ void __launch_bounds__(256, 3)
stats_kernel() {
    extern __shared__ __nv_bfloat16 sm[];
    int bx = blockIdx.x, m0 = blockIdx.y * 128;
    if (bx < 49)
        gemm_multi<128, 1, 4>(g_pooledS, g_headw, HEAD_N, 0, nullptr, 0, 0, 1,
                              nullptr, nullptr, 0, m0, bx * 256, sm);
    else if (bx < 98)
        gemm_multi<64, 1, 4>(g_h0S, g_t0o, CUT0, 0, nullptr, 0, 1, 0,
                             nullptr, nullptr, 0, m0, (bx - 49) * 256, sm);
    else
        gemm_multi<32, 1, 8>(g_h1S, g_t1o, N_T1, 0, nullptr, 0, 2, 0,
                             nullptr, nullptr, 0, m0, (bx - 98) * 512, sm);
}

__global__ void __launch_bounds__(256, 3)
store_kernel(float* __restrict__ out) {
    extern __shared__ __nv_bfloat16 sm[];
    int bx = blockIdx.x, m0 = blockIdx.y * 128;
    if (bx < 49)
        gemm_multi<128, 2, 4>(g_pooled, g_headw, HEAD_N, CUT0, out, 0, 0, 1,
                              nullptr, nullptr, 0, m0, bx * 256, sm);
    else if (bx < 98)
        gemm_multi<64, 2, 4>(g_h0, g_t0o, CUT0, CUT0, out, CUT0, 1, 0,
                             nullptr, nullptr, 0, m0, (bx - 49) * 256, sm);
    else
        gemm_multi<32, 2, 8>(g_h1, g_t1o, N_T1, N_T1, out, CUT1, 2, 0,
                             nullptr, nullptr, 0, m0, (bx - 98) * 512, sm);
}

// ---------------- combine per-tile sumexp -> per-row additive constants ----------------
__global__ void __launch_bounds__(256)
combine_kernel() {
    int r = blockIdx.x * 8 + (threadIdx.x >> 5);
    int lane = threadIdx.x & 31;
    const float* p0 = g_stats_s + (size_t)r * TILE_STRIDE;
    const float* p1 = g_stats_s + ((size_t)B_ROWS + r) * TILE_STRIDE;
    const float* p2 = g_stats_s + ((size_t)2 * B_ROWS + r) * TILE_STRIDE;
    float s0 = 0.f, s1 = 0.f, s2 = 0.f;
    #pragma unroll 4
    for (int t = lane; t < 391; t += 32) {
        if (t < 196) { s0 += p0[t]; s1 += p1[t]; }
        s2 += p2[t];
    }
    #pragma unroll
    for (int off = 16; off > 0; off >>= 1) {
        s0 += __shfl_xor_sync(0xffffffffu, s0, off);
        s1 += __shfl_xor_sync(0xffffffffu, s1, off);
        s2 += __shfl_xor_sync(0xffffffffu, s2, off);
    }
    if (lane == 0) {
        float l0 = logf(s0), l1 = logf(s1), l2 = logf(s2);
        g_adds[r * 3 + 0] = -l0;
        g_adds[r * 3 + 1] = g_extra[r * 2 + 0] * LN2 - l0 - l1;
        g_adds[r * 3 + 2] = g_extra[r * 2 + 1] * LN2 - l0 - l2;
    }
}

// ---------------- launch ----------------
extern "C" void kernel_launch(void* const* d_in, const int* in_sizes, int n_in,
                              void* d_out, int out_size) {
    const int*   x        = (const int*)d_in[0];
    const float* emb      = (const float*)d_in[1];
    const float* head_w_f = (const float*)d_in[2];
    const float* t0p_f    = (const float*)d_in[3];
    const float* t0o_f    = (const float*)d_in[4];
    const float* t1p_f    = (const float*)d_in[5];
    const float* t1o_f    = (const float*)d_in[6];
    float* out = (float*)d_out;

    // As(128x136) + 2x Ws(64x136), bf16
    const int SMB = (128 + 128) * (128 + 8) * (int)sizeof(__nv_bfloat16);  // 69632
    cudaFuncSetAttribute(stats_kernel, cudaFuncAttributeMaxDynamicSharedMemorySize, SMB);
    cudaFuncSetAttribute(store_kernel, cudaFuncAttributeMaxDynamicSharedMemorySize, SMB);
    cudaFuncSetAttribute(proj_kernel, cudaFuncAttributeMaxDynamicSharedMemorySize, SMB);

    prep_kernel<<<POOL_BLOCKS + CVT_BLOCKS, 256>>>(x, emb, head_w_f, t0o_f, t1o_f,
                                                   t0p_f, t1p_f);
    proj_kernel<<<dim3(2, 16), 256, SMB>>>();
    stats_kernel<<<dim3(147, 16), 256, SMB>>>();
    combine_kernel<<<B_ROWS / 8, 256>>>();
    store_kernel<<<dim3(147, 16), 256, SMB>>>(out);
}